// round 3
// baseline (speedup 1.0000x reference)
#include <cuda_runtime.h>

#define NVOX   262144
#define NU     65536
#define C_IN   128
#define C_HID  64
#define K_OUT  20
#define TILE   128
#define NTILES (NVOX / TILE)
#define FS     132          // fs row stride (floats), 16B-aligned rows, bank-spread
#define HS     130          // hs row stride (floats), 8B-aligned, bank-spread
#define THREADS 512

typedef unsigned long long u64;

// ---- f32x2 packed-FMA helpers (sm_103a FFMA2) ----
__device__ __forceinline__ u64 bcast2(float a) {
    u64 r; asm("mov.b64 %0, {%1, %1};" : "=l"(r) : "f"(a)); return r;
}
__device__ __forceinline__ u64 pack2(float a, float b) {
    u64 r; asm("mov.b64 %0, {%1, %2};" : "=l"(r) : "f"(a), "f"(b)); return r;
}
__device__ __forceinline__ void fma2(u64& d, u64 a, u64 b) {
    asm("fma.rn.f32x2 %0, %1, %2, %0;" : "+l"(d) : "l"(a), "l"(b));
}
__device__ __forceinline__ u64 add2(u64 a, u64 b) {
    u64 r; asm("add.rn.f32x2 %0, %1, %2;" : "=l"(r) : "l"(a), "l"(b)); return r;
}
__device__ __forceinline__ float2 unpk(u64 v) {
    float2 r; asm("mov.b64 {%0, %1}, %2;" : "=f"(r.x), "=f"(r.y) : "l"(v)); return r;
}

// Scratch: rank[v] = position in unmasked_idx, or -1 if masked.
__device__ int g_rank[NVOX];

__global__ void rank_kernel(const int* __restrict__ ui, const int* __restrict__ mi) {
    int t = blockIdx.x * blockDim.x + threadIdx.x;
    if (t < NU)        g_rank[ui[t]]      = t;
    else if (t < NVOX) g_rank[mi[t - NU]] = -1;
}

struct __align__(16) Smem {
    // resident weights
    float w1s [C_IN * C_HID];    // [c][j]
    float w2s [C_HID * C_IN];    // [j][c]
    float sdbs[C_IN * C_HID];    // [c][j]
    float sscs[C_HID * K_OUT];   // [j][k]
    float auxs[C_IN * K_OUT];    // [c][k]  (8B-aligned k-pairs)
    float b1s[C_HID], lngs[C_HID], lnbs[C_HID], sdbbs[C_HID];
    float b2s[C_IN];
    float sscbs[K_OUT];
    float auxbs[K_OUT];
    // per-tile staging
    float fs[C_IN * FS];         // [c][v]  feats -> vox (prior merged into masked cols)
    float hs[C_HID * HS];        // [j][v]  hidden, then d (GEMM3 out)
    float mus[TILE], rss[TILE];
    float red1[4 * TILE], red2[4 * TILE];
    int   ranks[TILE];
    int   lstv[TILE], lstr[TILE];
    int   cnt, pad[3];
};

__global__ void __launch_bounds__(THREADS, 1)
fused_kernel(const float* __restrict__ x3d,
             const float* __restrict__ w1,    const float* __restrict__ b1,
             const float* __restrict__ ln_g,  const float* __restrict__ ln_b,
             const float* __restrict__ w2,    const float* __restrict__ b2,
             const float* __restrict__ sdb_w, const float* __restrict__ sdb_b,
             const float* __restrict__ ssc_w, const float* __restrict__ ssc_b,
             const float* __restrict__ aux_w, const float* __restrict__ aux_b,
             float* __restrict__ out)
{
    extern __shared__ char smem_raw[];
    Smem* s = reinterpret_cast<Smem*>(smem_raw);
    const int t = threadIdx.x;

    // ---- one-time weight residency ----
    for (int i = t; i < C_IN * C_HID;  i += THREADS) s->w1s[i]  = w1[i];
    for (int i = t; i < C_HID * C_IN;  i += THREADS) s->w2s[i]  = w2[i];
    for (int i = t; i < C_IN * C_HID;  i += THREADS) s->sdbs[i] = sdb_w[i];
    for (int i = t; i < C_HID * K_OUT; i += THREADS) s->sscs[i] = ssc_w[i];
    for (int i = t; i < C_IN * K_OUT;  i += THREADS) s->auxs[i] = aux_w[i];
    if (t < C_HID) { s->b1s[t] = b1[t]; s->lngs[t] = ln_g[t]; s->lnbs[t] = ln_b[t]; s->sdbbs[t] = sdb_b[t]; }
    if (t < C_IN)  { s->b2s[t] = b2[t]; }
    if (t < K_OUT) { s->sscbs[t] = ssc_b[t]; s->auxbs[t] = aux_b[t]; }

    float* outsem = out + (size_t)K_OUT * NVOX;

    for (int tile = blockIdx.x; tile < NTILES; tile += gridDim.x) {
        const int vbase = tile * TILE;
        __syncthreads();                       // previous tile fully consumed
        if (t == 0) s->cnt = 0;

        // ---- load feats tile [128 c][128 v], coalesced float4 (4096 float4s) ----
        #pragma unroll
        for (int it = 0; it < 8; ++it) {
            int i  = t + it * THREADS;         // 0..4095 float4s
            int c  = i >> 5;
            int vq = i & 31;
            *reinterpret_cast<float4*>(&s->fs[c * FS + vq * 4]) =
                *reinterpret_cast<const float4*>(&x3d[(size_t)c * NVOX + vbase + vq * 4]);
        }
        if (t < TILE) s->ranks[t] = g_rank[vbase + t];
        __syncthreads();
        if (t < TILE) {
            int r = s->ranks[t];
            if (r >= 0) { int p = atomicAdd(&s->cnt, 1); s->lstv[p] = t; s->lstr[p] = r; }
        }

        // ---- GEMM1: h = feats @ w1 + b1  ([128v][64j], K=128), f32x2 over v-pairs ----
        {
            const int jg = t & 15, vg = t >> 4;          // 4 j's, 4 v's per thread
            u64 acc0[4] = {}, acc1[4] = {};
            const float* fptr = &s->fs[vg * 4];
            const float* wptr = &s->w1s[jg * 4];
            #pragma unroll 2
            for (int c = 0; c < C_IN; ++c) {
                u64 f0 = *reinterpret_cast<const u64*>(fptr + c * FS);
                u64 f1 = *reinterpret_cast<const u64*>(fptr + c * FS + 2);
                float4 w = *reinterpret_cast<const float4*>(wptr + c * C_HID);
                u64 wb;
                wb = bcast2(w.x); fma2(acc0[0], f0, wb); fma2(acc1[0], f1, wb);
                wb = bcast2(w.y); fma2(acc0[1], f0, wb); fma2(acc1[1], f1, wb);
                wb = bcast2(w.z); fma2(acc0[2], f0, wb); fma2(acc1[2], f1, wb);
                wb = bcast2(w.w); fma2(acc0[3], f0, wb); fma2(acc1[3], f1, wb);
            }
            #pragma unroll
            for (int jj = 0; jj < 4; ++jj) {
                int j = jg * 4 + jj;
                u64 bb = bcast2(s->b1s[j]);
                *reinterpret_cast<u64*>(&s->hs[j * HS + vg * 4])     = add2(acc0[jj], bb);
                *reinterpret_cast<u64*>(&s->hs[j * HS + vg * 4 + 2]) = add2(acc1[jj], bb);
            }
        }
        __syncthreads();

        // ---- LayerNorm over 64 j per voxel ----
        {
            int v = t & 127, q = t >> 7;
            float sum = 0.f, ssum = 0.f;
            #pragma unroll
            for (int jj = 0; jj < 16; ++jj) {
                float x = s->hs[(q * 16 + jj) * HS + v];
                sum += x; ssum += x * x;
            }
            s->red1[q * TILE + v] = sum;
            s->red2[q * TILE + v] = ssum;
        }
        __syncthreads();
        if (t < TILE) {
            float sum  = s->red1[t] + s->red1[TILE + t] + s->red1[2*TILE + t] + s->red1[3*TILE + t];
            float ssum = s->red2[t] + s->red2[TILE + t] + s->red2[2*TILE + t] + s->red2[3*TILE + t];
            float mu  = sum * (1.f / 64.f);
            float var = ssum * (1.f / 64.f) - mu * mu;
            s->mus[t] = mu;
            s->rss[t] = rsqrtf(var + 1e-5f);
        }
        __syncthreads();
        #pragma unroll
        for (int it = 0; it < 16; ++it) {
            int i = t + it * THREADS;          // 0..8191
            int j = i >> 7, v = i & 127;
            float x = s->hs[j * HS + v];
            x = (x - s->mus[v]) * s->rss[v] * s->lngs[j] + s->lnbs[j];
            s->hs[j * HS + v] = x > 0.f ? x : 0.01f * x;
        }
        __syncthreads();

        // ---- GEMM2: prior = h @ w2 + b2 ([128v][128c], K=64); merge into fs (masked) ----
        {
            const int vg2 = t & 15, cg = t >> 4;   // 8 v's, 4 c's per thread
            const int v0 = vg2 * 8, c0 = cg * 4;
            unsigned msk = 0;
            #pragma unroll
            for (int i = 0; i < 8; ++i) msk |= (s->ranks[v0 + i] < 0 ? 1u : 0u) << i;
            u64 acc[4][4] = {};
            const float* hp = &s->hs[v0];
            const float* wp = &s->w2s[c0];
            #pragma unroll 2
            for (int j = 0; j < C_HID; ++j) {
                u64 h0 = *reinterpret_cast<const u64*>(hp + j * HS);
                u64 h1 = *reinterpret_cast<const u64*>(hp + j * HS + 2);
                u64 h2 = *reinterpret_cast<const u64*>(hp + j * HS + 4);
                u64 h3 = *reinterpret_cast<const u64*>(hp + j * HS + 6);
                float4 w = *reinterpret_cast<const float4*>(wp + j * C_IN);
                u64 wb;
                wb = bcast2(w.x); fma2(acc[0][0],h0,wb); fma2(acc[0][1],h1,wb); fma2(acc[0][2],h2,wb); fma2(acc[0][3],h3,wb);
                wb = bcast2(w.y); fma2(acc[1][0],h0,wb); fma2(acc[1][1],h1,wb); fma2(acc[1][2],h2,wb); fma2(acc[1][3],h3,wb);
                wb = bcast2(w.z); fma2(acc[2][0],h0,wb); fma2(acc[2][1],h1,wb); fma2(acc[2][2],h2,wb); fma2(acc[2][3],h3,wb);
                wb = bcast2(w.w); fma2(acc[3][0],h0,wb); fma2(acc[3][1],h1,wb); fma2(acc[3][2],h2,wb); fma2(acc[3][3],h3,wb);
            }
            #pragma unroll
            for (int cc = 0; cc < 4; ++cc) {
                int c = c0 + cc;
                float b = s->b2s[c];
                float* frow = &s->fs[c * FS + v0];
                #pragma unroll
                for (int p = 0; p < 4; ++p) {
                    float2 pr = unpk(acc[cc][p]);
                    if (msk & (1u << (2*p)))     frow[2*p]     = pr.x + b;
                    if (msk & (1u << (2*p + 1))) frow[2*p + 1] = pr.y + b;
                }
            }
        }
        __syncthreads();

        // ---- GEMM3: d = leaky(vox @ sdb_w + sdb_b)  ([128v][64j], K=128) ----
        {
            const int jg = t & 15, vg = t >> 4;
            u64 acc0[4] = {}, acc1[4] = {};
            const float* fptr = &s->fs[vg * 4];
            const float* wptr = &s->sdbs[jg * 4];
            #pragma unroll 2
            for (int c = 0; c < C_IN; ++c) {
                u64 f0 = *reinterpret_cast<const u64*>(fptr + c * FS);
                u64 f1 = *reinterpret_cast<const u64*>(fptr + c * FS + 2);
                float4 w = *reinterpret_cast<const float4*>(wptr + c * C_HID);
                u64 wb;
                wb = bcast2(w.x); fma2(acc0[0], f0, wb); fma2(acc1[0], f1, wb);
                wb = bcast2(w.y); fma2(acc0[1], f0, wb); fma2(acc1[1], f1, wb);
                wb = bcast2(w.z); fma2(acc0[2], f0, wb); fma2(acc1[2], f1, wb);
                wb = bcast2(w.w); fma2(acc0[3], f0, wb); fma2(acc1[3], f1, wb);
            }
            #pragma unroll
            for (int jj = 0; jj < 4; ++jj) {
                int j = jg * 4 + jj;
                float b = s->sdbbs[j];
                float2 p0 = unpk(acc0[jj]), p1 = unpk(acc1[jj]);
                float x0 = p0.x + b; x0 = x0 > 0.f ? x0 : 0.01f * x0;
                float x1 = p0.y + b; x1 = x1 > 0.f ? x1 : 0.01f * x1;
                float x2 = p1.x + b; x2 = x2 > 0.f ? x2 : 0.01f * x2;
                float x3 = p1.y + b; x3 = x3 > 0.f ? x3 : 0.01f * x3;
                *reinterpret_cast<u64*>(&s->hs[j * HS + vg * 4])     = pack2(x0, x1);
                *reinterpret_cast<u64*>(&s->hs[j * HS + vg * 4 + 2]) = pack2(x2, x3);
            }
        }
        __syncthreads();

        // ---- GEMM4: ssc = d @ ssc_w + ssc_b -> out[k*NVOX + v] ----
        {
            int v = t & 127, k0 = (t >> 7) * 5;
            float acc[5] = {};
            #pragma unroll 4
            for (int j = 0; j < C_HID; ++j) {
                float dv = s->hs[j * HS + v];
                const float* wr = &s->sscs[j * K_OUT + k0];
                #pragma unroll
                for (int kk = 0; kk < 5; ++kk) acc[kk] += dv * wr[kk];
            }
            #pragma unroll
            for (int kk = 0; kk < 5; ++kk)
                out[(size_t)(k0 + kk) * NVOX + vbase + v] = acc[kk] + s->sscbs[k0 + kk];
        }

        // ---- AUX head: per-unmasked-voxel thread, 20 k as 10 f32x2 pairs ----
        if (t < s->cnt) {
            int v = s->lstv[t], r = s->lstr[t];
            u64 acc[10] = {};
            const float* fcol = &s->fs[v];
            #pragma unroll 2
            for (int c = 0; c < C_IN; ++c) {
                u64 fb = bcast2(fcol[c * FS]);
                const u64* wr = reinterpret_cast<const u64*>(&s->auxs[c * K_OUT]);
                #pragma unroll
                for (int i = 0; i < 10; ++i) fma2(acc[i], fb, wr[i]);
            }
            const u64* bb = reinterpret_cast<const u64*>(s->auxbs);
            float2* orow = reinterpret_cast<float2*>(&outsem[(size_t)r * K_OUT]);
            #pragma unroll
            for (int i = 0; i < 10; ++i) {
                float2 pr = unpk(add2(acc[i], bb[i]));
                orow[i] = pr;
            }
        }
    }
}

extern "C" void kernel_launch(void* const* d_in, const int* in_sizes, int n_in,
                              void* d_out, int out_size)
{
    const float* x3d   = (const float*)d_in[0];
    const float* w1    = (const float*)d_in[1];
    const float* b1    = (const float*)d_in[2];
    const float* ln_g  = (const float*)d_in[3];
    const float* ln_b  = (const float*)d_in[4];
    const float* w2    = (const float*)d_in[5];
    const float* b2    = (const float*)d_in[6];
    const float* sdb_w = (const float*)d_in[7];
    const float* sdb_b = (const float*)d_in[8];
    const float* ssc_w = (const float*)d_in[9];
    const float* ssc_b = (const float*)d_in[10];
    const float* aux_w = (const float*)d_in[11];
    const float* aux_b = (const float*)d_in[12];
    const int* ui      = (const int*)d_in[13];
    const int* mi      = (const int*)d_in[14];
    float* out         = (float*)d_out;

    int nsm = 0;
    cudaDeviceGetAttribute(&nsm, cudaDevAttrMultiProcessorCount, 0);
    if (nsm <= 0) nsm = 148;

    cudaFuncSetAttribute(fused_kernel,
                         cudaFuncAttributeMaxDynamicSharedMemorySize,
                         (int)sizeof(Smem));

    rank_kernel<<<NVOX / 256, 256>>>(ui, mi);
    fused_kernel<<<nsm, THREADS, sizeof(Smem)>>>(x3d, w1, b1, ln_g, ln_b, w2, b2,
                                                 sdb_w, sdb_b, ssc_w, ssc_b,
                                                 aux_w, aux_b, out);
}